// round 15
// baseline (speedup 1.0000x reference)
#include <cuda_runtime.h>
#include <cuda_fp16.h>
#include <cstdint>

// ---------------- problem constants ----------------
#define L_LAYERS 4
#define HID      1024
#define NC       256
#define NF       256
#define MB       8192
#define KCAT     512

#define ZSCALE     0.0009765625f   // 2^-10
#define USCALE_INV 1024.0f         // 2^10

// ---------------- GEMM tiling ----------------
#define BM 128
#define BN 128
#define BKH 64
#define STAGES 3
#define NTHREADS 256

#define ROW_BYTES 144
#define TILE_BYTES (128 * ROW_BYTES)
#define STAGE_BYTES (2 * TILE_BYTES)
#define SMEM_BYTES (STAGES * STAGE_BYTES)     // 110592

#define TILES_PER_LAYER 512
#define NJOBS (L_LAYERS * TILES_PER_LAYER)    // 2048
#define T_U   4                               // u-phase tiles
#define T_L0  12                              // tiles, layer 0
#define T_LN  28                              // tiles, layers 1-3

// ---------------- device scratch ----------------
__device__ __half g_Wcat[L_LAYERS * HID * KCAT];
__device__ __half g_Wut [L_LAYERS * HID * NF];
__device__ __half g_U   [(L_LAYERS - 1) * HID * HID];
__device__ float  g_bias[L_LAYERS * HID];
__device__ __half g_Xcat[MB * KCAT];
__device__ __half g_z0  [MB * HID];
__device__ __half g_z1  [MB * HID];
__device__ __half g_z2  [MB * HID];
__device__ int    g_ready[3][64];

// ---------------- helpers ----------------
__device__ __forceinline__ float softplus_f(float x) {
    return fmaxf(x, 0.0f) + log1pf(expf(-fabsf(x)));
}
__device__ __forceinline__ float mono_elem(float x, int k) {
    if (k < 8) { float sp = softplus_f(x); x = (k < 4) ? sp : -sp; }
    return x;
}
__device__ __forceinline__ uint2 pack4h(float a, float b, float c, float d) {
    __half2 lo = __floats2half2_rn(a, b);
    __half2 hi = __floats2half2_rn(c, d);
    uint2 r;
    r.x = *reinterpret_cast<uint32_t*>(&lo);
    r.y = *reinterpret_cast<uint32_t*>(&hi);
    return r;
}
__device__ __forceinline__ void cp_async16(uint32_t dst, const void* src) {
    asm volatile("cp.async.cg.shared.global [%0], [%1], 16;"
                 :: "r"(dst), "l"(src) : "memory");
}
__device__ __forceinline__ uint32_t smem_u32(const void* p) {
    uint32_t a;
    asm("{ .reg .u64 t; cvta.to.shared.u64 t, %1; cvt.u32.u64 %0, t; }"
        : "=r"(a) : "l"(p));
    return a;
}
__device__ __forceinline__ void ldmatrix_x4(uint32_t& r0, uint32_t& r1,
                                            uint32_t& r2, uint32_t& r3,
                                            uint32_t addr) {
    asm volatile("ldmatrix.sync.aligned.m8n8.x4.shared.b16 {%0,%1,%2,%3}, [%4];"
                 : "=r"(r0), "=r"(r1), "=r"(r2), "=r"(r3) : "r"(addr));
}
__device__ __forceinline__ __half* zbuf(int i) {
    return (i == 0) ? g_z0 : (i == 1) ? g_z1 : g_z2;
}

// ---------------- vectorized single prep kernel ----------------
#define WSEG (L_LAYERS * HID * 256)
#define USEG ((L_LAYERS - 1) * HID * HID)
#define XSEG (MB * KCAT)
#define W4 (WSEG / 4)
#define U4 (USEG / 4)
#define B4 ((L_LAYERS * HID) / 4)
#define X4 (XSEG / 4)
#define RSEG (3 * 64)

__global__ void prep_all_kernel(const float* __restrict__ Wc_w,
                                const float* __restrict__ Wu_w,
                                const float* __restrict__ Wut_w,
                                const float* __restrict__ rawU,
                                const float* __restrict__ Wc_b,
                                const float* __restrict__ Wu_b,
                                const float* __restrict__ xc,
                                const float* __restrict__ xf) {
    int idx = blockIdx.x * blockDim.x + threadIdx.x;
    if (idx < W4) {
        const int e = idx * 4;
        const int r = e >> 8, k = e & 255;
        float4 v = *reinterpret_cast<const float4*>(Wc_w + e);
        uint2 h = pack4h(mono_elem(v.x, k), mono_elem(v.y, k + 1),
                         mono_elem(v.z, k + 2), mono_elem(v.w, k + 3));
        *reinterpret_cast<uint2*>(&g_Wcat[(size_t)r * KCAT + k]) = h;
        return;
    }
    idx -= W4;
    if (idx < W4) {
        const int e = idx * 4;
        const int r = e >> 8, k = e & 255;
        float4 v = *reinterpret_cast<const float4*>(Wu_w + e);
        uint2 h = pack4h(mono_elem(v.x, k), mono_elem(v.y, k + 1),
                         mono_elem(v.z, k + 2), mono_elem(v.w, k + 3));
        *reinterpret_cast<uint2*>(&g_Wcat[(size_t)r * KCAT + 256 + k]) = h;
        return;
    }
    idx -= W4;
    if (idx < W4) {
        const int e = idx * 4;
        const int k = e & 255;
        float4 v = *reinterpret_cast<const float4*>(Wut_w + e);
        uint2 h = pack4h(mono_elem(v.x, k), mono_elem(v.y, k + 1),
                         mono_elem(v.z, k + 2), mono_elem(v.w, k + 3));
        *reinterpret_cast<uint2*>(&g_Wut[e]) = h;
        return;
    }
    idx -= W4;
    if (idx < U4) {
        const int e = idx * 4;
        float4 v = *reinterpret_cast<const float4*>(rawU + e);
        uint2 h = pack4h(softplus_f(v.x) * USCALE_INV,
                         softplus_f(v.y) * USCALE_INV,
                         softplus_f(v.z) * USCALE_INV,
                         softplus_f(v.w) * USCALE_INV);
        *reinterpret_cast<uint2*>(&g_U[e]) = h;
        return;
    }
    idx -= U4;
    if (idx < B4) {
        const int e = idx * 4;
        float4 a = *reinterpret_cast<const float4*>(Wc_b + e);
        float4 b = *reinterpret_cast<const float4*>(Wu_b + e);
        float4 o = make_float4(a.x + b.x, a.y + b.y, a.z + b.z, a.w + b.w);
        *reinterpret_cast<float4*>(&g_bias[e]) = o;
        return;
    }
    idx -= B4;
    if (idx < X4) {
        const int e = idx * 4;
        const int row = e >> 9, col = e & 511;
        const float* src = (col < 256) ? (xc + row * 256 + col)
                                       : (xf + row * 256 + (col - 256));
        float4 v = *reinterpret_cast<const float4*>(src);
        *reinterpret_cast<uint2*>(&g_Xcat[e]) = pack4h(v.x, v.y, v.z, v.w);
        return;
    }
    idx -= X4;
    if (idx < RSEG) {
        (&g_ready[0][0])[idx] = 0;
    }
}

// ---------------- persistent fused kernel (continuous tile stream) ----------------
struct SegSrc { const __half* X; int ldx; const __half* W; int ldw; int k0; };

// Tile t of job in layer `layer`:  t<4: u-phase; t<12: Wcat; else: U
__device__ __forceinline__ SegSrc seg_src2(int layer, int t,
                                           const __half* __restrict__ Xcat) {
    SegSrc s;
    if (t < T_U) {
        s.X = Xcat + 256; s.ldx = KCAT;
        s.W = g_Wut + (size_t)layer * HID * NF; s.ldw = NF;
        s.k0 = t * BKH;
    } else if (t < T_U + 8) {
        s.X = Xcat; s.ldx = KCAT;
        s.W = g_Wcat + (size_t)layer * HID * KCAT; s.ldw = KCAT;
        s.k0 = (t - T_U) * BKH;
    } else {
        s.X = zbuf(layer - 1); s.ldx = HID;
        s.W = g_U + (size_t)(layer - 1) * HID * HID; s.ldw = HID;
        s.k0 = (t - T_U - 8) * BKH;
    }
    return s;
}

__device__ __forceinline__ void load_tile_f16(uint32_t sA, uint32_t sB,
                                              const SegSrc s, int bm, int bn, int tid) {
    #pragma unroll
    for (int j = 0; j < 4; j++) {
        const int f = tid + NTHREADS * j;
        const int row = f >> 3, c = f & 7;
        cp_async16(sA + row * ROW_BYTES + c * 16,
                   s.X + (size_t)(bm + row) * s.ldx + s.k0 + c * 8);
        cp_async16(sB + row * ROW_BYTES + c * 16,
                   s.W + (size_t)(bn + row) * s.ldw + s.k0 + c * 8);
    }
    asm volatile("cp.async.commit_group;" ::: "memory");
}

__global__ void __launch_bounds__(NTHREADS, 2)
icnn_persistent(const __half* __restrict__ Xcat,
                const float* __restrict__ WutB,
                float* __restrict__ out)
{
    extern __shared__ __align__(16) char dsm[];
    const uint32_t sbase = smem_u32(dsm);

    const int tid  = threadIdx.x;
    const int lane = tid & 31;
    const int wid  = tid >> 5;
    const int wm   = wid & 3;
    const int wn   = wid >> 2;
    const int lk   = lane & 3;
    const int lr   = lane >> 2;

    uint32_t aOff[2];
    #pragma unroll
    for (int mi = 0; mi < 2; mi++) {
        const int row = wm * 32 + mi * 16 + (lane & 15);
        aOff[mi] = row * ROW_BYTES + ((lane >> 4) << 4);
    }
    uint32_t bOff[4];
    #pragma unroll
    for (int ni2 = 0; ni2 < 4; ni2++) {
        const int n = wn * 64 + ni2 * 16 + (lane & 7) + ((lane >> 4) << 3);
        bOff[ni2] = n * ROW_BYTES + (((lane >> 3) & 1) << 4);
    }

    int gt3 = 0;          // running stage-phase (sum of T mod 3)
    bool first = true;

    for (int job = blockIdx.x; job < NJOBS; job += gridDim.x) {
        const int layer = job >> 9;
        const int tile  = job & 511;
        const int bmb   = tile >> 3;
        const int bm    = bmb * BM;
        const int bn    = (tile & 7) * BN;
        const int T     = layer ? T_LN : T_L0;
        const int nj    = job + gridDim.x;
        const bool has_next = (nj < NJOBS);

        const float* bias_u = WutB + layer * HID;
        const float* bias_z = g_bias + layer * HID;

        float2 bu[8], bz[8];
        #pragma unroll
        for (int ni = 0; ni < 8; ni++) {
            const int c = bn + wn * 64 + ni * 8 + lk * 2;
            bu[ni] = *reinterpret_cast<const float2*>(&bias_u[c]);
            bz[ni] = *reinterpret_cast<const float2*>(&bias_z[c]);
        }

        float acc[2][8][4];
        #pragma unroll
        for (int mi = 0; mi < 2; mi++)
            #pragma unroll
            for (int ni = 0; ni < 8; ni++)
                #pragma unroll
                for (int q = 0; q < 4; q++) acc[mi][ni][q] = 0.0f;

        if (first) {        // cold prologue: only for each CTA's very first job
            first = false;
            #pragma unroll
            for (int p = 0; p < 2; p++) {
                SegSrc s = seg_src2(layer, p, Xcat);
                const int st = (gt3 + p) % 3;
                load_tile_f16(sbase + st * STAGE_BYTES,
                              sbase + st * STAGE_BYTES + TILE_BYTES, s, bm, bn, tid);
            }
        }

        for (int t = 0; t < T; t++) {
            if (t == T_U) {   // u = relu(u_acc + bias_u)
                #pragma unroll
                for (int mi = 0; mi < 2; mi++)
                    #pragma unroll
                    for (int ni = 0; ni < 8; ni++) {
                        acc[mi][ni][0] = fmaxf(acc[mi][ni][0] + bu[ni].x, 0.0f);
                        acc[mi][ni][1] = fmaxf(acc[mi][ni][1] + bu[ni].y, 0.0f);
                        acc[mi][ni][2] = fmaxf(acc[mi][ni][2] + bu[ni].x, 0.0f);
                        acc[mi][ni][3] = fmaxf(acc[mi][ni][3] + bu[ni].y, 0.0f);
                    }
            }

            // wait: tile t's group complete. Groups retire in commit order, and
            // at most 2 newer groups are in flight, so wait_group 1 suffices —
            // except on this CTA's final tile when nothing newer was issued.
            if (t == T - 1 && !has_next)
                asm volatile("cp.async.wait_group 0;" ::: "memory");
            else
                asm volatile("cp.async.wait_group 1;" ::: "memory");
            __syncthreads();

            const int pf = t + 2;
            if (pf < T) {
                if (layer > 0 && pf == T_U + 8) {   // first U-phase prefetch
                    if (tid == 0) {
                        volatile int* c = &g_ready[layer - 1][bmb];
                        while (*c < 8) __nanosleep(64);
                    }
                    __syncthreads();
                    __threadfence();
                }
                SegSrc s = seg_src2(layer, pf, Xcat);
                const int st = (gt3 + pf) % 3;
                load_tile_f16(sbase + st * STAGE_BYTES,
                              sbase + st * STAGE_BYTES + TILE_BYTES, s, bm, bn, tid);
            } else if (has_next) {
                // stream next job's u-phase tiles (0/1): dep-free by construction
                const int nt    = pf - T;           // 0 or 1
                const int nlay  = nj >> 9;
                const int ntile = nj & 511;
                const int nbm   = (ntile >> 3) * BM;
                const int nbn   = (ntile & 7) * BN;
                SegSrc s = seg_src2(nlay, nt, Xcat);
                const int st = (gt3 + pf) % 3;
                load_tile_f16(sbase + st * STAGE_BYTES,
                              sbase + st * STAGE_BYTES + TILE_BYTES, s, nbm, nbn, tid);
            }

            const int stc = (gt3 + t) % 3;
            const uint32_t stA = sbase + stc * STAGE_BYTES;
            const uint32_t stB = stA + TILE_BYTES;

            #pragma unroll
            for (int kk = 0; kk < BKH; kk += 16) {
                uint32_t a[2][4], b[8][2];
                #pragma unroll
                for (int mi = 0; mi < 2; mi++)
                    ldmatrix_x4(a[mi][0], a[mi][1], a[mi][2], a[mi][3],
                                stA + aOff[mi] + kk * 2);
                #pragma unroll
                for (int ni2 = 0; ni2 < 4; ni2++)
                    ldmatrix_x4(b[2*ni2][0], b[2*ni2][1], b[2*ni2+1][0], b[2*ni2+1][1],
                                stB + bOff[ni2] + kk * 2);
                #pragma unroll
                for (int mi = 0; mi < 2; mi++) {
                    #pragma unroll
                    for (int ni = 0; ni < 8; ni++) {
                        asm volatile(
                            "mma.sync.aligned.m16n8k16.row.col.f32.f16.f16.f32 "
                            "{%0,%1,%2,%3}, {%4,%5,%6,%7}, {%8,%9}, {%0,%1,%2,%3};"
                            : "+f"(acc[mi][ni][0]), "+f"(acc[mi][ni][1]),
                              "+f"(acc[mi][ni][2]), "+f"(acc[mi][ni][3])
                            : "r"(a[mi][0]), "r"(a[mi][1]),
                              "r"(a[mi][2]), "r"(a[mi][3]),
                              "r"(b[ni][0]), "r"(b[ni][1]));
                    }
                }
            }
        }
        gt3 = (gt3 + T) % 3;

        // -------- epilogue: z = relu(acc + bias_z) (overlaps next job's loads) --------
        const bool last = (layer == L_LAYERS - 1);
        __half* outH = last ? nullptr : zbuf(layer);
        #pragma unroll
        for (int mi = 0; mi < 2; mi++) {
            const int r0 = bm + wm * 32 + mi * 16 + lr;
            const int r1 = r0 + 8;
            #pragma unroll
            for (int ni = 0; ni < 8; ni++) {
                const int c = bn + wn * 64 + ni * 8 + lk * 2;
                float v0 = fmaxf(acc[mi][ni][0] + bz[ni].x, 0.0f);
                float v1 = fmaxf(acc[mi][ni][1] + bz[ni].y, 0.0f);
                float v2 = fmaxf(acc[mi][ni][2] + bz[ni].x, 0.0f);
                float v3 = fmaxf(acc[mi][ni][3] + bz[ni].y, 0.0f);
                if (!last) {
                    *reinterpret_cast<__half2*>(&outH[(size_t)r0 * HID + c]) =
                        __floats2half2_rn(v0 * ZSCALE, v1 * ZSCALE);
                    *reinterpret_cast<__half2*>(&outH[(size_t)r1 * HID + c]) =
                        __floats2half2_rn(v2 * ZSCALE, v3 * ZSCALE);
                } else {
                    *reinterpret_cast<float2*>(&out[(size_t)r0 * HID + c]) =
                        make_float2(v0, v1);
                    *reinterpret_cast<float2*>(&out[(size_t)r1 * HID + c]) =
                        make_float2(v2, v3);
                }
            }
        }

        __threadfence();
        __syncthreads();
        if (!last && tid == 0)
            atomicAdd(&g_ready[layer][bmb], 1);
    }
}

// ---------------- launch ----------------
extern "C" void kernel_launch(void* const* d_in, const int* in_sizes, int n_in,
                              void* d_out, int out_size) {
    const float* xc    = (const float*)d_in[0];
    const float* xf    = (const float*)d_in[1];
    const float* Wc_w  = (const float*)d_in[2];
    const float* Wc_b  = (const float*)d_in[3];
    const float* Wu_w  = (const float*)d_in[4];
    const float* Wu_b  = (const float*)d_in[5];
    const float* Wut_w = (const float*)d_in[6];
    const float* Wut_b = (const float*)d_in[7];
    const float* rawU  = (const float*)d_in[8];
    float* out = (float*)d_out;

    __half* gXcat;
    cudaGetSymbolAddress((void**)&gXcat, g_Xcat);

    static int nsm = 0;
    if (nsm == 0) {
        cudaDeviceGetAttribute(&nsm, cudaDevAttrMultiProcessorCount, 0);
        cudaFuncSetAttribute(icnn_persistent,
                             cudaFuncAttributeMaxDynamicSharedMemorySize, SMEM_BYTES);
    }

    {
        const int tot = 3 * W4 + U4 + B4 + X4 + RSEG;
        prep_all_kernel<<<(tot + 255) / 256, 256>>>(Wc_w, Wu_w, Wut_w,
                                                    rawU, Wc_b, Wu_b, xc, xf);
    }

    icnn_persistent<<<2 * nsm, NTHREADS, SMEM_BYTES>>>(gXcat, Wut_b, out);
}

// round 16
// speedup vs baseline: 1.0313x; 1.0313x over previous
#include <cuda_runtime.h>
#include <cuda_fp16.h>
#include <cstdint>

// ---------------- problem constants ----------------
#define L_LAYERS 4
#define HID      1024
#define NC       256
#define NF       256
#define MB       8192
#define KCAT     512

#define ZSCALE     0.0009765625f   // 2^-10
#define USCALE_INV 1024.0f         // 2^10

// ---------------- GEMM tiling ----------------
#define BM 128
#define BN 128
#define BKH 64
#define STAGES 3
#define NTHREADS 256

#define ROW_BYTES 144
#define TILE_BYTES (128 * ROW_BYTES)
#define STAGE_BYTES (2 * TILE_BYTES)
#define SMEM_BYTES (STAGES * STAGE_BYTES)     // 110592

#define TILES_PER_LAYER 512
#define NJOBS (L_LAYERS * TILES_PER_LAYER)    // 2048

// ---------------- device scratch ----------------
__device__ __half g_Wcat[L_LAYERS * HID * KCAT];
__device__ __half g_Wut [L_LAYERS * HID * NF];
__device__ __half g_U   [(L_LAYERS - 1) * HID * HID];
__device__ float  g_bias[L_LAYERS * HID];
__device__ __half g_Xcat[MB * KCAT];
__device__ __half g_z0  [MB * HID];
__device__ __half g_z1  [MB * HID];
__device__ __half g_z2  [MB * HID];
__device__ int    g_ready[3][64];

// ---------------- helpers ----------------
__device__ __forceinline__ float softplus_f(float x) {
    return fmaxf(x, 0.0f) + log1pf(expf(-fabsf(x)));
}
__device__ __forceinline__ float mono_elem(float x, int k) {
    if (k < 8) { float sp = softplus_f(x); x = (k < 4) ? sp : -sp; }
    return x;
}
__device__ __forceinline__ uint2 pack4h(float a, float b, float c, float d) {
    __half2 lo = __floats2half2_rn(a, b);
    __half2 hi = __floats2half2_rn(c, d);
    uint2 r;
    r.x = *reinterpret_cast<uint32_t*>(&lo);
    r.y = *reinterpret_cast<uint32_t*>(&hi);
    return r;
}
__device__ __forceinline__ void cp_async16(uint32_t dst, const void* src) {
    asm volatile("cp.async.cg.shared.global [%0], [%1], 16;"
                 :: "r"(dst), "l"(src) : "memory");
}
__device__ __forceinline__ uint32_t smem_u32(const void* p) {
    uint32_t a;
    asm("{ .reg .u64 t; cvta.to.shared.u64 t, %1; cvt.u32.u64 %0, t; }"
        : "=r"(a) : "l"(p));
    return a;
}
__device__ __forceinline__ void ldmatrix_x4(uint32_t& r0, uint32_t& r1,
                                            uint32_t& r2, uint32_t& r3,
                                            uint32_t addr) {
    asm volatile("ldmatrix.sync.aligned.m8n8.x4.shared.b16 {%0,%1,%2,%3}, [%4];"
                 : "=r"(r0), "=r"(r1), "=r"(r2), "=r"(r3) : "r"(addr));
}

// ---------------- vectorized single prep kernel ----------------
#define WSEG (L_LAYERS * HID * 256)
#define USEG ((L_LAYERS - 1) * HID * HID)
#define XSEG (MB * KCAT)
#define W4 (WSEG / 4)
#define U4 (USEG / 4)
#define B4 ((L_LAYERS * HID) / 4)
#define X4 (XSEG / 4)
#define RSEG (3 * 64)

__global__ void prep_all_kernel(const float* __restrict__ Wc_w,
                                const float* __restrict__ Wu_w,
                                const float* __restrict__ Wut_w,
                                const float* __restrict__ rawU,
                                const float* __restrict__ Wc_b,
                                const float* __restrict__ Wu_b,
                                const float* __restrict__ xc,
                                const float* __restrict__ xf) {
    int idx = blockIdx.x * blockDim.x + threadIdx.x;
    if (idx < W4) {
        const int e = idx * 4;
        const int r = e >> 8, k = e & 255;
        float4 v = *reinterpret_cast<const float4*>(Wc_w + e);
        uint2 h = pack4h(mono_elem(v.x, k), mono_elem(v.y, k + 1),
                         mono_elem(v.z, k + 2), mono_elem(v.w, k + 3));
        *reinterpret_cast<uint2*>(&g_Wcat[(size_t)r * KCAT + k]) = h;
        return;
    }
    idx -= W4;
    if (idx < W4) {
        const int e = idx * 4;
        const int r = e >> 8, k = e & 255;
        float4 v = *reinterpret_cast<const float4*>(Wu_w + e);
        uint2 h = pack4h(mono_elem(v.x, k), mono_elem(v.y, k + 1),
                         mono_elem(v.z, k + 2), mono_elem(v.w, k + 3));
        *reinterpret_cast<uint2*>(&g_Wcat[(size_t)r * KCAT + 256 + k]) = h;
        return;
    }
    idx -= W4;
    if (idx < W4) {
        const int e = idx * 4;
        const int k = e & 255;
        float4 v = *reinterpret_cast<const float4*>(Wut_w + e);
        uint2 h = pack4h(mono_elem(v.x, k), mono_elem(v.y, k + 1),
                         mono_elem(v.z, k + 2), mono_elem(v.w, k + 3));
        *reinterpret_cast<uint2*>(&g_Wut[e]) = h;
        return;
    }
    idx -= W4;
    if (idx < U4) {
        const int e = idx * 4;
        float4 v = *reinterpret_cast<const float4*>(rawU + e);
        uint2 h = pack4h(softplus_f(v.x) * USCALE_INV,
                         softplus_f(v.y) * USCALE_INV,
                         softplus_f(v.z) * USCALE_INV,
                         softplus_f(v.w) * USCALE_INV);
        *reinterpret_cast<uint2*>(&g_U[e]) = h;
        return;
    }
    idx -= U4;
    if (idx < B4) {
        const int e = idx * 4;
        float4 a = *reinterpret_cast<const float4*>(Wc_b + e);
        float4 b = *reinterpret_cast<const float4*>(Wu_b + e);
        float4 o = make_float4(a.x + b.x, a.y + b.y, a.z + b.z, a.w + b.w);
        *reinterpret_cast<float4*>(&g_bias[e]) = o;
        return;
    }
    idx -= B4;
    if (idx < X4) {
        const int e = idx * 4;
        const int row = e >> 9, col = e & 511;
        const float* src = (col < 256) ? (xc + row * 256 + col)
                                       : (xf + row * 256 + (col - 256));
        float4 v = *reinterpret_cast<const float4*>(src);
        *reinterpret_cast<uint2*>(&g_Xcat[e]) = pack4h(v.x, v.y, v.z, v.w);
        return;
    }
    idx -= X4;
    if (idx < RSEG) {
        (&g_ready[0][0])[idx] = 0;
    }
}

// ---------------- persistent fused kernel (all layers) ----------------
struct SegSrc { const __half* X; int ldx; const __half* W; int ldw; int k0; };

__device__ __forceinline__ SegSrc seg_src(int t, int tU,
    const __half* Xu, const __half* Wut,
    const __half* Xc, const __half* Wc,
    const __half* Zp, const __half* U) {
    SegSrc s;
    if (t < tU)            { s.X = Xu; s.ldx = KCAT; s.W = Wut; s.ldw = NF;   s.k0 = t * BKH; }
    else if (t < tU + 8)   { s.X = Xc; s.ldx = KCAT; s.W = Wc;  s.ldw = KCAT; s.k0 = (t - tU) * BKH; }
    else                   { s.X = Zp; s.ldx = HID;  s.W = U;   s.ldw = HID;  s.k0 = (t - tU - 8) * BKH; }
    return s;
}

__device__ __forceinline__ void load_tile_f16(uint32_t sA, uint32_t sB,
                                              const SegSrc s, int bm, int bn, int tid) {
    #pragma unroll
    for (int j = 0; j < 4; j++) {
        const int f = tid + NTHREADS * j;
        const int row = f >> 3, c = f & 7;
        cp_async16(sA + row * ROW_BYTES + c * 16,
                   s.X + (size_t)(bm + row) * s.ldx + s.k0 + c * 8);
        cp_async16(sB + row * ROW_BYTES + c * 16,
                   s.W + (size_t)(bn + row) * s.ldw + s.k0 + c * 8);
    }
    asm volatile("cp.async.commit_group;" ::: "memory");
}

__global__ void __launch_bounds__(NTHREADS, 2)
icnn_persistent(const __half* __restrict__ Xcat,
                const float* __restrict__ WutB,
                float* __restrict__ out)
{
    extern __shared__ __align__(16) char dsm[];
    const uint32_t sbase = smem_u32(dsm);

    const int tid  = threadIdx.x;
    const int lane = tid & 31;
    const int wid  = tid >> 5;
    const int wm   = wid & 3;
    const int wn   = wid >> 2;
    const int lk   = lane & 3;
    const int lr   = lane >> 2;

    __half* zbufs[3] = {g_z0, g_z1, g_z2};

    uint32_t aOff[2];
    #pragma unroll
    for (int mi = 0; mi < 2; mi++) {
        const int row = wm * 32 + mi * 16 + (lane & 15);
        aOff[mi] = row * ROW_BYTES + ((lane >> 4) << 4);
    }
    uint32_t bOff[4];
    #pragma unroll
    for (int ni2 = 0; ni2 < 4; ni2++) {
        const int n = wn * 64 + ni2 * 16 + (lane & 7) + ((lane >> 4) << 3);
        bOff[ni2] = n * ROW_BYTES + (((lane >> 3) & 1) << 4);
    }

    for (int job = blockIdx.x; job < NJOBS; job += gridDim.x) {
        const int layer = job >> 9;
        const int tile  = job & 511;
        const int bmb   = tile >> 3;
        const int bm    = bmb * BM;
        const int bn    = (tile & 7) * BN;

        const __half* Wut  = g_Wut  + (size_t)layer * HID * NF;
        const __half* Wcat = g_Wcat + (size_t)layer * HID * KCAT;
        const __half* U    = layer ? (g_U + (size_t)(layer - 1) * HID * HID) : nullptr;
        const __half* Zp   = layer ? zbufs[layer - 1] : nullptr;
        const float* bias_u = WutB + layer * HID;
        const float* bias_z = g_bias + layer * HID;
        const __half* Xu = Xcat + 256;

        const int tU = NF / BKH;             // 4
        const int T  = layer ? (tU + KCAT / BKH + HID / BKH) : (tU + KCAT / BKH);

        float2 bu[8], bz[8];
        #pragma unroll
        for (int ni = 0; ni < 8; ni++) {
            const int c = bn + wn * 64 + ni * 8 + lk * 2;
            bu[ni] = *reinterpret_cast<const float2*>(&bias_u[c]);
            bz[ni] = *reinterpret_cast<const float2*>(&bias_z[c]);
        }

        float acc[2][8][4];
        #pragma unroll
        for (int mi = 0; mi < 2; mi++)
            #pragma unroll
            for (int ni = 0; ni < 8; ni++)
                #pragma unroll
                for (int q = 0; q < 4; q++) acc[mi][ni][q] = 0.0f;

        #pragma unroll
        for (int p = 0; p < STAGES - 1; p++) {
            SegSrc s = seg_src(p, tU, Xu, Wut, Xcat, Wcat, Zp, U);
            load_tile_f16(sbase + p * STAGE_BYTES,
                          sbase + p * STAGE_BYTES + TILE_BYTES, s, bm, bn, tid);
        }

        for (int t = 0; t < T; t++) {
            if (t == tU) {   // u = relu(u_acc + bias_u)
                #pragma unroll
                for (int mi = 0; mi < 2; mi++)
                    #pragma unroll
                    for (int ni = 0; ni < 8; ni++) {
                        acc[mi][ni][0] = fmaxf(acc[mi][ni][0] + bu[ni].x, 0.0f);
                        acc[mi][ni][1] = fmaxf(acc[mi][ni][1] + bu[ni].y, 0.0f);
                        acc[mi][ni][2] = fmaxf(acc[mi][ni][2] + bu[ni].x, 0.0f);
                        acc[mi][ni][3] = fmaxf(acc[mi][ni][3] + bu[ni].y, 0.0f);
                    }
            }

            if (t < T - 1) asm volatile("cp.async.wait_group 1;" ::: "memory");
            else           asm volatile("cp.async.wait_group 0;" ::: "memory");
            __syncthreads();

            const int pf = t + STAGES - 1;
            if (layer > 0 && pf == tU + 8) {
                if (tid == 0) {
                    volatile int* c = &g_ready[layer - 1][bmb];
                    while (*c < 8) __nanosleep(64);
                }
                __syncthreads();
                __threadfence();
            }
            if (pf < T) {
                SegSrc s = seg_src(pf, tU, Xu, Wut, Xcat, Wcat, Zp, U);
                const int ps = pf % STAGES;
                load_tile_f16(sbase + ps * STAGE_BYTES,
                              sbase + ps * STAGE_BYTES + TILE_BYTES, s, bm, bn, tid);
            }

            const uint32_t stA = sbase + (t % STAGES) * STAGE_BYTES;
            const uint32_t stB = stA + TILE_BYTES;

            #pragma unroll
            for (int kk = 0; kk < BKH; kk += 16) {
                uint32_t a[2][4], b[8][2];
                #pragma unroll
                for (int mi = 0; mi < 2; mi++)
                    ldmatrix_x4(a[mi][0], a[mi][1], a[mi][2], a[mi][3],
                                stA + aOff[mi] + kk * 2);
                #pragma unroll
                for (int ni2 = 0; ni2 < 4; ni2++)
                    ldmatrix_x4(b[2*ni2][0], b[2*ni2][1], b[2*ni2+1][0], b[2*ni2+1][1],
                                stB + bOff[ni2] + kk * 2);
                #pragma unroll
                for (int mi = 0; mi < 2; mi++) {
                    #pragma unroll
                    for (int ni = 0; ni < 8; ni++) {
                        asm volatile(
                            "mma.sync.aligned.m16n8k16.row.col.f32.f16.f16.f32 "
                            "{%0,%1,%2,%3}, {%4,%5,%6,%7}, {%8,%9}, {%0,%1,%2,%3};"
                            : "+f"(acc[mi][ni][0]), "+f"(acc[mi][ni][1]),
                              "+f"(acc[mi][ni][2]), "+f"(acc[mi][ni][3])
                            : "r"(a[mi][0]), "r"(a[mi][1]),
                              "r"(a[mi][2]), "r"(a[mi][3]),
                              "r"(b[ni][0]), "r"(b[ni][1]));
                    }
                }
            }
        }

        // -------- epilogue: z = relu(acc + bias_z) --------
        const bool last = (layer == L_LAYERS - 1);
        __half* outH = last ? nullptr : zbufs[layer];
        #pragma unroll
        for (int mi = 0; mi < 2; mi++) {
            const int r0 = bm + wm * 32 + mi * 16 + lr;
            const int r1 = r0 + 8;
            #pragma unroll
            for (int ni = 0; ni < 8; ni++) {
                const int c = bn + wn * 64 + ni * 8 + lk * 2;
                float v0 = fmaxf(acc[mi][ni][0] + bz[ni].x, 0.0f);
                float v1 = fmaxf(acc[mi][ni][1] + bz[ni].y, 0.0f);
                float v2 = fmaxf(acc[mi][ni][2] + bz[ni].x, 0.0f);
                float v3 = fmaxf(acc[mi][ni][3] + bz[ni].y, 0.0f);
                if (!last) {
                    *reinterpret_cast<__half2*>(&outH[(size_t)r0 * HID + c]) =
                        __floats2half2_rn(v0 * ZSCALE, v1 * ZSCALE);
                    *reinterpret_cast<__half2*>(&outH[(size_t)r1 * HID + c]) =
                        __floats2half2_rn(v2 * ZSCALE, v3 * ZSCALE);
                } else {
                    *reinterpret_cast<float2*>(&out[(size_t)r0 * HID + c]) =
                        make_float2(v0, v1);
                    *reinterpret_cast<float2*>(&out[(size_t)r1 * HID + c]) =
                        make_float2(v2, v3);
                }
            }
        }

        __threadfence();
        __syncthreads();
        if (!last && tid == 0)
            atomicAdd(&g_ready[layer][bmb], 1);
    }
}

// ---------------- launch ----------------
extern "C" void kernel_launch(void* const* d_in, const int* in_sizes, int n_in,
                              void* d_out, int out_size) {
    const float* xc    = (const float*)d_in[0];
    const float* xf    = (const float*)d_in[1];
    const float* Wc_w  = (const float*)d_in[2];
    const float* Wc_b  = (const float*)d_in[3];
    const float* Wu_w  = (const float*)d_in[4];
    const float* Wu_b  = (const float*)d_in[5];
    const float* Wut_w = (const float*)d_in[6];
    const float* Wut_b = (const float*)d_in[7];
    const float* rawU  = (const float*)d_in[8];
    float* out = (float*)d_out;

    __half* gXcat;
    cudaGetSymbolAddress((void**)&gXcat, g_Xcat);

    static int nsm = 0;
    if (nsm == 0) {
        cudaDeviceGetAttribute(&nsm, cudaDevAttrMultiProcessorCount, 0);
        cudaFuncSetAttribute(icnn_persistent,
                             cudaFuncAttributeMaxDynamicSharedMemorySize, SMEM_BYTES);
    }

    {
        const int tot = 3 * W4 + U4 + B4 + X4 + RSEG;
        prep_all_kernel<<<(tot + 255) / 256, 256>>>(Wc_w, Wu_w, Wut_w,
                                                    rawU, Wc_b, Wu_b, xc, xf);
    }

    icnn_persistent<<<2 * nsm, NTHREADS, SMEM_BYTES>>>(gXcat, Wut_b, out);
}

// round 17
// speedup vs baseline: 1.0454x; 1.0137x over previous
#include <cuda_runtime.h>
#include <cuda_fp16.h>
#include <cstdint>

// ---------------- problem constants ----------------
#define L_LAYERS 4
#define HID      1024
#define NC       256
#define NF       256
#define MB       8192
#define KCAT     512

#define ZSCALE     0.0009765625f   // 2^-10
#define USCALE_INV 1024.0f         // 2^10

// ---------------- GEMM tiling ----------------
#define BM 128
#define BN 128
#define BKH 64
#define STAGES 3
#define NTHREADS 256

#define ROW_BYTES 144
#define TILE_BYTES (128 * ROW_BYTES)
#define STAGE_BYTES (2 * TILE_BYTES)
#define SMEM_BYTES (STAGES * STAGE_BYTES)     // 110592

#define TILES_PER_LAYER 512
#define NJOBS (L_LAYERS * TILES_PER_LAYER)    // 2048

// ---------------- device scratch ----------------
__device__ __half g_Wcat[L_LAYERS * HID * KCAT];
__device__ __half g_Wut [L_LAYERS * HID * NF];
__device__ __half g_U   [(L_LAYERS - 1) * HID * HID];
__device__ float  g_bias[L_LAYERS * HID];
__device__ __half g_Xcat[MB * KCAT];
__device__ __half g_z0  [MB * HID];
__device__ __half g_z1  [MB * HID];
__device__ __half g_z2  [MB * HID];
__device__ int    g_ready[3][64];

// ---------------- helpers ----------------
__device__ __forceinline__ float softplus_f(float x) {
    return fmaxf(x, 0.0f) + log1pf(expf(-fabsf(x)));
}
__device__ __forceinline__ float mono_elem(float x, int k) {
    if (k < 8) { float sp = softplus_f(x); x = (k < 4) ? sp : -sp; }
    return x;
}
__device__ __forceinline__ uint2 pack4h(float a, float b, float c, float d) {
    __half2 lo = __floats2half2_rn(a, b);
    __half2 hi = __floats2half2_rn(c, d);
    uint2 r;
    r.x = *reinterpret_cast<uint32_t*>(&lo);
    r.y = *reinterpret_cast<uint32_t*>(&hi);
    return r;
}
__device__ __forceinline__ void cp_async16(uint32_t dst, const void* src) {
    asm volatile("cp.async.cg.shared.global [%0], [%1], 16;"
                 :: "r"(dst), "l"(src) : "memory");
}
__device__ __forceinline__ uint32_t smem_u32(const void* p) {
    uint32_t a;
    asm("{ .reg .u64 t; cvta.to.shared.u64 t, %1; cvt.u32.u64 %0, t; }"
        : "=r"(a) : "l"(p));
    return a;
}
__device__ __forceinline__ void ldmatrix_x4(uint32_t& r0, uint32_t& r1,
                                            uint32_t& r2, uint32_t& r3,
                                            uint32_t addr) {
    asm volatile("ldmatrix.sync.aligned.m8n8.x4.shared.b16 {%0,%1,%2,%3}, [%4];"
                 : "=r"(r0), "=r"(r1), "=r"(r2), "=r"(r3) : "r"(addr));
}
__device__ __forceinline__ void signal_release(int* p) {
    asm volatile("red.release.gpu.global.add.s32 [%0], 1;" :: "l"(p) : "memory");
}
__device__ __forceinline__ int load_acquire(const int* p) {
    int v;
    asm volatile("ld.acquire.gpu.global.s32 %0, [%1];" : "=r"(v) : "l"(p) : "memory");
    return v;
}

// ---------------- vectorized single prep kernel ----------------
#define WSEG (L_LAYERS * HID * 256)
#define USEG ((L_LAYERS - 1) * HID * HID)
#define XSEG (MB * KCAT)
#define W4 (WSEG / 4)
#define U4 (USEG / 4)
#define B4 ((L_LAYERS * HID) / 4)
#define X4 (XSEG / 4)
#define RSEG (3 * 64)

__global__ void prep_all_kernel(const float* __restrict__ Wc_w,
                                const float* __restrict__ Wu_w,
                                const float* __restrict__ Wut_w,
                                const float* __restrict__ rawU,
                                const float* __restrict__ Wc_b,
                                const float* __restrict__ Wu_b,
                                const float* __restrict__ xc,
                                const float* __restrict__ xf) {
    int idx = blockIdx.x * blockDim.x + threadIdx.x;
    if (idx < W4) {
        const int e = idx * 4;
        const int r = e >> 8, k = e & 255;
        float4 v = *reinterpret_cast<const float4*>(Wc_w + e);
        uint2 h = pack4h(mono_elem(v.x, k), mono_elem(v.y, k + 1),
                         mono_elem(v.z, k + 2), mono_elem(v.w, k + 3));
        *reinterpret_cast<uint2*>(&g_Wcat[(size_t)r * KCAT + k]) = h;
        return;
    }
    idx -= W4;
    if (idx < W4) {
        const int e = idx * 4;
        const int r = e >> 8, k = e & 255;
        float4 v = *reinterpret_cast<const float4*>(Wu_w + e);
        uint2 h = pack4h(mono_elem(v.x, k), mono_elem(v.y, k + 1),
                         mono_elem(v.z, k + 2), mono_elem(v.w, k + 3));
        *reinterpret_cast<uint2*>(&g_Wcat[(size_t)r * KCAT + 256 + k]) = h;
        return;
    }
    idx -= W4;
    if (idx < W4) {
        const int e = idx * 4;
        const int k = e & 255;
        float4 v = *reinterpret_cast<const float4*>(Wut_w + e);
        uint2 h = pack4h(mono_elem(v.x, k), mono_elem(v.y, k + 1),
                         mono_elem(v.z, k + 2), mono_elem(v.w, k + 3));
        *reinterpret_cast<uint2*>(&g_Wut[e]) = h;
        return;
    }
    idx -= W4;
    if (idx < U4) {
        const int e = idx * 4;
        float4 v = *reinterpret_cast<const float4*>(rawU + e);
        uint2 h = pack4h(softplus_f(v.x) * USCALE_INV,
                         softplus_f(v.y) * USCALE_INV,
                         softplus_f(v.z) * USCALE_INV,
                         softplus_f(v.w) * USCALE_INV);
        *reinterpret_cast<uint2*>(&g_U[e]) = h;
        return;
    }
    idx -= U4;
    if (idx < B4) {
        const int e = idx * 4;
        float4 a = *reinterpret_cast<const float4*>(Wc_b + e);
        float4 b = *reinterpret_cast<const float4*>(Wu_b + e);
        float4 o = make_float4(a.x + b.x, a.y + b.y, a.z + b.z, a.w + b.w);
        *reinterpret_cast<float4*>(&g_bias[e]) = o;
        return;
    }
    idx -= B4;
    if (idx < X4) {
        const int e = idx * 4;
        const int row = e >> 9, col = e & 511;
        const float* src = (col < 256) ? (xc + row * 256 + col)
                                       : (xf + row * 256 + (col - 256));
        float4 v = *reinterpret_cast<const float4*>(src);
        *reinterpret_cast<uint2*>(&g_Xcat[e]) = pack4h(v.x, v.y, v.z, v.w);
        return;
    }
    idx -= X4;
    if (idx < RSEG) {
        (&g_ready[0][0])[idx] = 0;
    }
}

// ---------------- persistent fused kernel (all layers) ----------------
struct SegSrc { const __half* X; int ldx; const __half* W; int ldw; int k0; };

__device__ __forceinline__ SegSrc seg_src(int t, int tU,
    const __half* Xu, const __half* Wut,
    const __half* Xc, const __half* Wc,
    const __half* Zp, const __half* U) {
    SegSrc s;
    if (t < tU)            { s.X = Xu; s.ldx = KCAT; s.W = Wut; s.ldw = NF;   s.k0 = t * BKH; }
    else if (t < tU + 8)   { s.X = Xc; s.ldx = KCAT; s.W = Wc;  s.ldw = KCAT; s.k0 = (t - tU) * BKH; }
    else                   { s.X = Zp; s.ldx = HID;  s.W = U;   s.ldw = HID;  s.k0 = (t - tU - 8) * BKH; }
    return s;
}

__device__ __forceinline__ void load_tile_f16(uint32_t sA, uint32_t sB,
                                              const SegSrc s, int bm, int bn, int tid) {
    #pragma unroll
    for (int j = 0; j < 4; j++) {
        const int f = tid + NTHREADS * j;
        const int row = f >> 3, c = f & 7;
        cp_async16(sA + row * ROW_BYTES + c * 16,
                   s.X + (size_t)(bm + row) * s.ldx + s.k0 + c * 8);
        cp_async16(sB + row * ROW_BYTES + c * 16,
                   s.W + (size_t)(bn + row) * s.ldw + s.k0 + c * 8);
    }
    asm volatile("cp.async.commit_group;" ::: "memory");
}

__global__ void __launch_bounds__(NTHREADS, 2)
icnn_persistent(const __half* __restrict__ Xcat,
                const float* __restrict__ WutB,
                float* __restrict__ out)
{
    extern __shared__ __align__(16) char dsm[];
    const uint32_t sbase = smem_u32(dsm);

    const int tid  = threadIdx.x;
    const int lane = tid & 31;
    const int wid  = tid >> 5;
    const int wm   = wid & 3;
    const int wn   = wid >> 2;
    const int lk   = lane & 3;
    const int lr   = lane >> 2;

    __half* zbufs[3] = {g_z0, g_z1, g_z2};

    uint32_t aOff[2];
    #pragma unroll
    for (int mi = 0; mi < 2; mi++) {
        const int row = wm * 32 + mi * 16 + (lane & 15);
        aOff[mi] = row * ROW_BYTES + ((lane >> 4) << 4);
    }
    uint32_t bOff[4];
    #pragma unroll
    for (int ni2 = 0; ni2 < 4; ni2++) {
        const int n = wn * 64 + ni2 * 16 + (lane & 7) + ((lane >> 4) << 3);
        bOff[ni2] = n * ROW_BYTES + (((lane >> 3) & 1) << 4);
    }

    for (int job = blockIdx.x; job < NJOBS; job += gridDim.x) {
        const int layer = job >> 9;
        const int tile  = job & 511;
        const int bmb   = tile >> 3;
        const int bm    = bmb * BM;
        const int bn    = (tile & 7) * BN;

        const __half* Wut  = g_Wut  + (size_t)layer * HID * NF;
        const __half* Wcat = g_Wcat + (size_t)layer * HID * KCAT;
        const __half* U    = layer ? (g_U + (size_t)(layer - 1) * HID * HID) : nullptr;
        const __half* Zp   = layer ? zbufs[layer - 1] : nullptr;
        const float* bias_u = WutB + layer * HID;
        const float* bias_z = g_bias + layer * HID;
        const __half* Xu = Xcat + 256;

        const int tU = NF / BKH;             // 4
        const int T  = layer ? (tU + KCAT / BKH + HID / BKH) : (tU + KCAT / BKH);

        float2 bu[8], bz[8];
        #pragma unroll
        for (int ni = 0; ni < 8; ni++) {
            const int c = bn + wn * 64 + ni * 8 + lk * 2;
            bu[ni] = *reinterpret_cast<const float2*>(&bias_u[c]);
            bz[ni] = *reinterpret_cast<const float2*>(&bias_z[c]);
        }

        float acc[2][8][4];
        #pragma unroll
        for (int mi = 0; mi < 2; mi++)
            #pragma unroll
            for (int ni = 0; ni < 8; ni++)
                #pragma unroll
                for (int q = 0; q < 4; q++) acc[mi][ni][q] = 0.0f;

        #pragma unroll
        for (int p = 0; p < STAGES - 1; p++) {
            SegSrc s = seg_src(p, tU, Xu, Wut, Xcat, Wcat, Zp, U);
            load_tile_f16(sbase + p * STAGE_BYTES,
                          sbase + p * STAGE_BYTES + TILE_BYTES, s, bm, bn, tid);
        }

        for (int t = 0; t < T; t++) {
            if (t == tU) {   // u = relu(u_acc + bias_u)
                #pragma unroll
                for (int mi = 0; mi < 2; mi++)
                    #pragma unroll
                    for (int ni = 0; ni < 8; ni++) {
                        acc[mi][ni][0] = fmaxf(acc[mi][ni][0] + bu[ni].x, 0.0f);
                        acc[mi][ni][1] = fmaxf(acc[mi][ni][1] + bu[ni].y, 0.0f);
                        acc[mi][ni][2] = fmaxf(acc[mi][ni][2] + bu[ni].x, 0.0f);
                        acc[mi][ni][3] = fmaxf(acc[mi][ni][3] + bu[ni].y, 0.0f);
                    }
            }

            if (t < T - 1) asm volatile("cp.async.wait_group 1;" ::: "memory");
            else           asm volatile("cp.async.wait_group 0;" ::: "memory");
            __syncthreads();

            const int pf = t + STAGES - 1;
            if (layer > 0 && pf == tU + 8) {
                if (tid == 0) {
                    const int* c = &g_ready[layer - 1][bmb];
                    while (load_acquire(c) < 8) __nanosleep(64);
                }
                __syncthreads();   // happens-before: tid0's acquire -> all threads
            }
            if (pf < T) {
                SegSrc s = seg_src(pf, tU, Xu, Wut, Xcat, Wcat, Zp, U);
                const int ps = pf % STAGES;
                load_tile_f16(sbase + ps * STAGE_BYTES,
                              sbase + ps * STAGE_BYTES + TILE_BYTES, s, bm, bn, tid);
            }

            const uint32_t stA = sbase + (t % STAGES) * STAGE_BYTES;
            const uint32_t stB = stA + TILE_BYTES;

            #pragma unroll
            for (int kk = 0; kk < BKH; kk += 16) {
                uint32_t a[2][4], b[8][2];
                #pragma unroll
                for (int mi = 0; mi < 2; mi++)
                    ldmatrix_x4(a[mi][0], a[mi][1], a[mi][2], a[mi][3],
                                stA + aOff[mi] + kk * 2);
                #pragma unroll
                for (int ni2 = 0; ni2 < 4; ni2++)
                    ldmatrix_x4(b[2*ni2][0], b[2*ni2][1], b[2*ni2+1][0], b[2*ni2+1][1],
                                stB + bOff[ni2] + kk * 2);
                #pragma unroll
                for (int mi = 0; mi < 2; mi++) {
                    #pragma unroll
                    for (int ni = 0; ni < 8; ni++) {
                        asm volatile(
                            "mma.sync.aligned.m16n8k16.row.col.f32.f16.f16.f32 "
                            "{%0,%1,%2,%3}, {%4,%5,%6,%7}, {%8,%9}, {%0,%1,%2,%3};"
                            : "+f"(acc[mi][ni][0]), "+f"(acc[mi][ni][1]),
                              "+f"(acc[mi][ni][2]), "+f"(acc[mi][ni][3])
                            : "r"(a[mi][0]), "r"(a[mi][1]),
                              "r"(a[mi][2]), "r"(a[mi][3]),
                              "r"(b[ni][0]), "r"(b[ni][1]));
                    }
                }
            }
        }

        // -------- epilogue: z = relu(acc + bias_z) --------
        const bool last = (layer == L_LAYERS - 1);
        __half* outH = last ? nullptr : zbufs[layer];
        #pragma unroll
        for (int mi = 0; mi < 2; mi++) {
            const int r0 = bm + wm * 32 + mi * 16 + lr;
            const int r1 = r0 + 8;
            #pragma unroll
            for (int ni = 0; ni < 8; ni++) {
                const int c = bn + wn * 64 + ni * 8 + lk * 2;
                float v0 = fmaxf(acc[mi][ni][0] + bz[ni].x, 0.0f);
                float v1 = fmaxf(acc[mi][ni][1] + bz[ni].y, 0.0f);
                float v2 = fmaxf(acc[mi][ni][2] + bz[ni].x, 0.0f);
                float v3 = fmaxf(acc[mi][ni][3] + bz[ni].y, 0.0f);
                if (!last) {
                    *reinterpret_cast<__half2*>(&outH[(size_t)r0 * HID + c]) =
                        __floats2half2_rn(v0 * ZSCALE, v1 * ZSCALE);
                    *reinterpret_cast<__half2*>(&outH[(size_t)r1 * HID + c]) =
                        __floats2half2_rn(v2 * ZSCALE, v3 * ZSCALE);
                } else {
                    *reinterpret_cast<float2*>(&out[(size_t)r0 * HID + c]) =
                        make_float2(v0, v1);
                    *reinterpret_cast<float2*>(&out[(size_t)r1 * HID + c]) =
                        make_float2(v2, v3);
                }
            }
        }

        // all threads' stores -> barrier -> single release-signal (no all-thread MEMBAR)
        __syncthreads();
        if (!last && tid == 0)
            signal_release(&g_ready[layer][bmb]);
    }
}

// ---------------- launch ----------------
extern "C" void kernel_launch(void* const* d_in, const int* in_sizes, int n_in,
                              void* d_out, int out_size) {
    const float* xc    = (const float*)d_in[0];
    const float* xf    = (const float*)d_in[1];
    const float* Wc_w  = (const float*)d_in[2];
    const float* Wc_b  = (const float*)d_in[3];
    const float* Wu_w  = (const float*)d_in[4];
    const float* Wu_b  = (const float*)d_in[5];
    const float* Wut_w = (const float*)d_in[6];
    const float* Wut_b = (const float*)d_in[7];
    const float* rawU  = (const float*)d_in[8];
    float* out = (float*)d_out;

    __half* gXcat;
    cudaGetSymbolAddress((void**)&gXcat, g_Xcat);

    static int nsm = 0;
    if (nsm == 0) {
        cudaDeviceGetAttribute(&nsm, cudaDevAttrMultiProcessorCount, 0);
        cudaFuncSetAttribute(icnn_persistent,
                             cudaFuncAttributeMaxDynamicSharedMemorySize, SMEM_BYTES);
    }

    {
        const int tot = 3 * W4 + U4 + B4 + X4 + RSEG;
        prep_all_kernel<<<(tot + 255) / 256, 256>>>(Wc_w, Wu_w, Wut_w,
                                                    rawU, Wc_b, Wu_b, xc, xf);
    }

    icnn_persistent<<<2 * nsm, NTHREADS, SMEM_BYTES>>>(gXcat, Wut_b, out);
}